// round 2
// baseline (speedup 1.0000x reference)
#include <cuda_runtime.h>
#include <cuda_fp16.h>
#include <cstdint>

#define OUT_F   4096
#define IN_F    4096
#define M_TOTAL 16384
#define TILE_M  128
#define TILE_N  128
#define TILE_K  32
#define NKTILES (IN_F / TILE_K)          /* 128 */
#define NSTAGE  4

/* SMEM: padded rows — 32 halves data + pad to 80 bytes (conflict-free
   ldmatrix: bank start = (20*row + 4*chunk) % 32, distinct for row 0..7) */
#define ROW_BYTES   80
#define OP_BYTES    (128 * ROW_BYTES)            /* 10240 per operand      */
#define STAGE_BYTES (2 * OP_BYTES)               /* 20480 A+B              */
#define SM_TOTAL    (NSTAGE * STAGE_BYTES)       /* 81920                  */

/* fp16 operand scratch (device globals are the sanctioned scratch path) */
__device__ __half g_Wh[(size_t)OUT_F * IN_F];        /*  32 MB */
__device__ __half g_Xh[(size_t)M_TOTAL * IN_F];      /* 128 MB */

/* ---------------- helpers ---------------- */
__device__ __forceinline__ uint32_t smem_u32(const void* p) {
    uint32_t a;
    asm("{ .reg .u64 t; cvta.to.shared.u64 t, %1; cvt.u32.u64 %0, t; }"
        : "=r"(a) : "l"(p));
    return a;
}
__device__ __forceinline__ void cp16(uint32_t dst, const void* src) {
    asm volatile("cp.async.cg.shared.global [%0], [%1], 16;" :: "r"(dst), "l"(src));
}
__device__ __forceinline__ void ldmatrix_x4(uint32_t* r, uint32_t addr) {
    asm volatile("ldmatrix.sync.aligned.m8n8.x4.shared.b16 {%0,%1,%2,%3}, [%4];"
                 : "=r"(r[0]), "=r"(r[1]), "=r"(r[2]), "=r"(r[3]) : "r"(addr));
}
__device__ __forceinline__ void mma_f16(float* c, const uint32_t* a,
                                        uint32_t b0, uint32_t b1) {
    asm volatile(
        "mma.sync.aligned.m16n8k16.row.col.f32.f16.f16.f32 "
        "{%0,%1,%2,%3}, {%4,%5,%6,%7}, {%8,%9}, {%0,%1,%2,%3};"
        : "+f"(c[0]), "+f"(c[1]), "+f"(c[2]), "+f"(c[3])
        : "r"(a[0]), "r"(a[1]), "r"(a[2]), "r"(a[3]), "r"(b0), "r"(b1));
}

/* -------- pass 1: dequant W -> fp16 --------
   flat f = g*262144 + j ; o = g*64 + (j>>12), i = j&4095
   equivalently (o,i): g = o>>6 is within-group idx, group id j = (o&63)*4096 + i */
__global__ void __launch_bounds__(256) dequant_kernel(
    const int* __restrict__ Wq, const float* __restrict__ scale,
    const float* __restrict__ zero)
{
    int t = blockIdx.x * 256 + threadIdx.x;   /* 4 elems per thread */
    int e = t << 2;
    int o = e >> 12;
    int i = e & 4095;
    int g = o >> 6;
    int j = ((o & 63) << 12) + i;
    int4   q = *reinterpret_cast<const int4*>(Wq + (size_t)g * 262144 + j);
    float4 s = *reinterpret_cast<const float4*>(scale + j);
    float4 z = *reinterpret_cast<const float4*>(zero + j);
    __half2 h0 = __floats2half2_rn(((float)q.x - z.x) * s.x,
                                   ((float)q.y - z.y) * s.y);
    __half2 h1 = __floats2half2_rn(((float)q.z - z.z) * s.z,
                                   ((float)q.w - z.w) * s.w);
    uint2 pk;
    pk.x = *reinterpret_cast<uint32_t*>(&h0);
    pk.y = *reinterpret_cast<uint32_t*>(&h1);
    *reinterpret_cast<uint2*>(g_Wh + (size_t)o * IN_F + i) = pk;
}

/* -------- pass 2: x -> fp16 -------- */
__global__ void __launch_bounds__(256) xconv_kernel(const float* __restrict__ x)
{
    size_t t = (size_t)blockIdx.x * 256 + threadIdx.x;
    float4 v = reinterpret_cast<const float4*>(x)[t];
    __half2 h0 = __floats2half2_rn(v.x, v.y);
    __half2 h1 = __floats2half2_rn(v.z, v.w);
    uint2 pk;
    pk.x = *reinterpret_cast<uint32_t*>(&h0);
    pk.y = *reinterpret_cast<uint32_t*>(&h1);
    reinterpret_cast<uint2*>(g_Xh)[t] = pk;
}

/* -------- pass 3: fp16 mma.sync GEMM, 128x128x32, 4-stage cp.async -------- */
__global__ void __launch_bounds__(256)
gemm_kernel(const float* __restrict__ bias, float* __restrict__ out)
{
    extern __shared__ char smem[];
    const uint32_t sb = smem_u32(smem);
    const int tid  = threadIdx.x;
    const int wid  = tid >> 5, lane = tid & 31;
    const int m0   = blockIdx.y * TILE_M;
    const int n0   = blockIdx.x * TILE_N;
    const int wm   = wid >> 2;          /* 0..1 : 64 M rows   */
    const int wn   = wid & 3;           /* 0..3 : 32 N cols   */

    /* loader geometry: warp w, iter j -> rows (w*16 + j*8 + lane%8), chunk lane/8 */
    const int ld_row0 = wid * 16 + (lane & 7);
    const int ld_ch   = lane >> 3;                       /* 0..3 (8 halves each) */
    const uint32_t ld_soff = (uint32_t)(ld_row0 * ROW_BYTES + ld_ch * 16);
    const __half* Abase = g_Xh + (size_t)(m0 + ld_row0) * IN_F + ld_ch * 8;
    const __half* Bbase = g_Wh + (size_t)(n0 + ld_row0) * IN_F + ld_ch * 8;

#define PREFETCH(KT) do {                                                      \
        int _kt = (KT);                                                        \
        uint32_t _st = sb + (uint32_t)((_kt & (NSTAGE - 1)) * STAGE_BYTES);    \
        const __half* _a = Abase + _kt * TILE_K;                               \
        const __half* _b = Bbase + _kt * TILE_K;                               \
        cp16(_st + ld_soff,                      _a);                          \
        cp16(_st + ld_soff + 8 * ROW_BYTES,      _a + 8 * IN_F);               \
        cp16(_st + OP_BYTES + ld_soff,                 _b);                    \
        cp16(_st + OP_BYTES + ld_soff + 8 * ROW_BYTES, _b + 8 * IN_F);         \
        asm volatile("cp.async.commit_group;" ::: "memory");                   \
    } while (0)

    PREFETCH(0); PREFETCH(1); PREFETCH(2);

    float acc[4][4][4];                 /* [mt][nt][c] : 64 M x 32 N */
#pragma unroll
    for (int a = 0; a < 4; a++)
#pragma unroll
        for (int b = 0; b < 4; b++)
#pragma unroll
            for (int c = 0; c < 4; c++) acc[a][b][c] = 0.f;

    /* ldmatrix addresses (within a stage) */
    const uint32_t a_row = (uint32_t)(wm * 64 + (lane & 15));
    const uint32_t b_row = (uint32_t)(wn * 32 + (lane & 15));
    const uint32_t hi    = (uint32_t)(lane >> 4);        /* chunk select bit  */

    for (int kt = 0; kt < NKTILES; kt++) {
        if (kt < NKTILES - 2)
            asm volatile("cp.async.wait_group 2;" ::: "memory");
        else if (kt == NKTILES - 2)
            asm volatile("cp.async.wait_group 1;" ::: "memory");
        else
            asm volatile("cp.async.wait_group 0;" ::: "memory");
        __syncthreads();

        if (kt + 3 < NKTILES) PREFETCH(kt + 3);

        const uint32_t st = sb + (uint32_t)((kt & (NSTAGE - 1)) * STAGE_BYTES);
#pragma unroll
        for (int ks = 0; ks < 2; ks++) {                 /* two k16 steps */
            const uint32_t ch = (uint32_t)(ks * 2) + hi; /* 16B chunk idx */
            uint32_t afr[4][4], bfr[2][4];
#pragma unroll
            for (int mt = 0; mt < 4; mt++)
                ldmatrix_x4(afr[mt],
                            st + (a_row + mt * 16) * ROW_BYTES + ch * 16);
#pragma unroll
            for (int nt2 = 0; nt2 < 2; nt2++)
                ldmatrix_x4(bfr[nt2],
                            st + OP_BYTES + (b_row + nt2 * 16) * ROW_BYTES + ch * 16);
#pragma unroll
            for (int mt = 0; mt < 4; mt++)
#pragma unroll
                for (int nt = 0; nt < 4; nt++)
                    mma_f16(acc[mt][nt], afr[mt],
                            bfr[nt >> 1][(nt & 1)], bfr[nt >> 1][(nt & 1) + 2]);
        }
    }

    /* epilogue: acc + bias -> out ; thread (lane) owns rows lane/4 (+8),
       cols (lane%4)*2, (+1) within each 16x8 tile */
    const int rbase = lane >> 2;
    const int cbase = (lane & 3) * 2;
#pragma unroll
    for (int mt = 0; mt < 4; mt++) {
        const int m = m0 + wm * 64 + mt * 16 + rbase;
#pragma unroll
        for (int nt = 0; nt < 4; nt++) {
            const int n = n0 + wn * 32 + nt * 8 + cbase;
            float2 bv = *reinterpret_cast<const float2*>(bias + n);
            float2 v0, v1;
            v0.x = acc[mt][nt][0] + bv.x;
            v0.y = acc[mt][nt][1] + bv.y;
            v1.x = acc[mt][nt][2] + bv.x;
            v1.y = acc[mt][nt][3] + bv.y;
            *reinterpret_cast<float2*>(out + (size_t)m * OUT_F + n)       = v0;
            *reinterpret_cast<float2*>(out + (size_t)(m + 8) * OUT_F + n) = v1;
        }
    }
}

/* ---------------- launch ---------------- */
extern "C" void kernel_launch(void* const* d_in, const int* in_sizes, int n_in,
                              void* d_out, int out_size)
{
    const float* x     = (const float*)d_in[0];
    const int*   Wq    = (const int*)  d_in[1];
    const float* scale = (const float*)d_in[2];
    const float* zero  = (const float*)d_in[3];
    const float* bias  = (const float*)d_in[4];
    float*       out   = (float*)d_out;

    dequant_kernel<<<(OUT_F * IN_F / 4) / 256, 256>>>(Wq, scale, zero);
    xconv_kernel<<<(M_TOTAL * IN_F / 4) / 256, 256>>>(x);

    cudaFuncSetAttribute(gemm_kernel,
                         cudaFuncAttributeMaxDynamicSharedMemorySize, SM_TOTAL);
    dim3 grid(OUT_F / TILE_N, M_TOTAL / TILE_M);     /* (32, 128) x-fastest */
    gemm_kernel<<<grid, 256, SM_TOTAL>>>(bias, out);
}